// round 5
// baseline (speedup 1.0000x reference)
#include <cuda_runtime.h>
#include <cuda_fp16.h>
#include <cstdint>

// ---------------- problem constants ----------------
#define NB      16384
#define F_IN    768
#define F_OUT   512
#define TILE_M  128          // batch rows per CTA
#define NHALF   256          // N columns per pass
#define KC      64           // K elements per SMEM chunk (fp16)
#define NKC     (F_IN / KC)  // 12 chunks
#define THREADS 256

#define ROWB    144          // padded SMEM row stride in bytes (72 fp16) -> conflict-free
#define A_BUF_B (TILE_M * ROWB)   // 18432
#define B_BUF_B (NHALF  * ROWB)   // 36864

// smem layout (bytes, dynamic)
#define SM_B1    0                       // 512 f
#define SM_W2    2048                    // 1024 f
#define SM_PACC  6144                    // 128 f
#define SM_A     6912                    // 2 x 18432
#define SM_B     (6912 + 2*A_BUF_B)      // 2 x 36864
#define SMEM_TOTAL (SM_B + 2*B_BUF_B)    // 117504 bytes

// ---------------- fp16 scratch (device globals: allowed) ----------------
__device__ __align__(16) __half g_a16[2 * NB * F_IN];   // [stm | nstm]
__device__ __align__(16) __half g_w16[F_OUT * F_IN];

// ---------------- helpers ----------------
__device__ __forceinline__ uint32_t smem_u32(const void* p) {
    uint32_t a;
    asm("{ .reg .u64 t; cvta.to.shared.u64 t, %1; cvt.u32.u64 %0, t; }" : "=r"(a) : "l"(p));
    return a;
}

__device__ __forceinline__ void cp_async16(uint32_t dst, const void* src) {
    asm volatile("cp.async.cg.shared.global [%0], [%1], 16;\n" :: "r"(dst), "l"(src) : "memory");
}
__device__ __forceinline__ void cp_commit() {
    asm volatile("cp.async.commit_group;\n" ::: "memory");
}
template <int N>
__device__ __forceinline__ void cp_wait() {
    asm volatile("cp.async.wait_group %0;\n" :: "n"(N) : "memory");
}

__device__ __forceinline__ void mma16816(float& c0, float& c1, float& c2, float& c3,
                                         uint32_t a0, uint32_t a1, uint32_t a2, uint32_t a3,
                                         uint32_t b0, uint32_t b1) {
    asm volatile(
        "mma.sync.aligned.m16n8k16.row.col.f32.f16.f16.f32 "
        "{%0,%1,%2,%3}, {%4,%5,%6,%7}, {%8,%9}, {%0,%1,%2,%3};"
        : "+f"(c0), "+f"(c1), "+f"(c2), "+f"(c3)
        : "r"(a0), "r"(a1), "r"(a2), "r"(a3), "r"(b0), "r"(b1));
}

// ---------------- prologue: fp32 -> fp16 convert ----------------
__global__ void cvt_kernel(const float* __restrict__ stm,
                           const float* __restrict__ nstm,
                           const float* __restrict__ W1) {
    const int n1_4 = NB * F_IN / 4;             // float4 count per activation tensor
    const int nw_4 = F_OUT * F_IN / 4;
    const int total = 2 * n1_4 + nw_4;
    for (int i = blockIdx.x * blockDim.x + threadIdx.x; i < total;
         i += gridDim.x * blockDim.x) {
        const float4* src;
        __half* dst;
        int j;
        if (i < n1_4) {
            src = (const float4*)stm;  dst = g_a16;               j = i;
        } else if (i < 2 * n1_4) {
            src = (const float4*)nstm; dst = g_a16 + NB * F_IN;   j = i - n1_4;
        } else {
            src = (const float4*)W1;   dst = g_w16;               j = i - 2 * n1_4;
        }
        float4 v = src[j];
        __half2 h0 = __floats2half2_rn(v.x, v.y);
        __half2 h1 = __floats2half2_rn(v.z, v.w);
        uint2 packed;
        packed.x = *(uint32_t*)&h0;
        packed.y = *(uint32_t*)&h1;
        ((uint2*)dst)[j] = packed;
    }
}

// ---------------- main fused kernel ----------------
__global__ void __launch_bounds__(THREADS, 1)
pnet_kernel(const float* __restrict__ b1, const float* __restrict__ W2,
            const float* __restrict__ b2, float* __restrict__ out)
{
    extern __shared__ char smem[];
    const uint32_t sbase = smem_u32(smem);
    const int tid  = threadIdx.x;
    const int wid  = tid >> 5;
    const int lane = tid & 31;
    const int gid  = lane >> 2;   // group-of-4 id (row index within 8)
    const int tig  = lane & 3;    // thread-in-group (col pairs / k pairs)

    const int warpM = (wid & 1) * 64;   // 2 warps along M
    const int warpN = (wid >> 1) * 64;  // 4 warps along N (within the 256 half)

    float* b1s  = (float*)(smem + SM_B1);
    float* w2s  = (float*)(smem + SM_W2);
    float* pacc = (float*)(smem + SM_PACC);

    for (int i = tid; i < F_OUT; i += THREADS)     b1s[i] = b1[i];
    for (int i = tid; i < 2 * F_OUT; i += THREADS) w2s[i] = W2[i];
    if (tid < TILE_M) pacc[tid] = 0.0f;
    __syncthreads();

    const int rowbase = blockIdx.x * TILE_M;

    for (int p = 0; p < 2; p++) {
        const __half* abase = g_a16 + (size_t)p * NB * F_IN + (size_t)rowbase * F_IN;

        for (int nh = 0; nh < 2; nh++) {
            const __half* wbase = g_w16 + (size_t)nh * NHALF * F_IN;

            float acc[4][8][4];
            #pragma unroll
            for (int mt = 0; mt < 4; mt++)
                #pragma unroll
                for (int nt = 0; nt < 8; nt++)
                    #pragma unroll
                    for (int e = 0; e < 4; e++) acc[mt][nt][e] = 0.0f;

            // ---- issue chunk 0 ----
            {
                const __half* asrc = abase;          // kc=0
                const __half* wsrc = wbase;
                #pragma unroll
                for (int it = 0; it < 4; it++) {     // A: 1024 16B-ops
                    int idx = tid + it * THREADS;
                    int r = idx >> 3, c = idx & 7;
                    cp_async16(sbase + SM_A + r * ROWB + c * 16,
                               asrc + (size_t)r * F_IN + c * 8);
                }
                #pragma unroll
                for (int it = 0; it < 8; it++) {     // B: 2048 16B-ops
                    int idx = tid + it * THREADS;
                    int r = idx >> 3, c = idx & 7;
                    cp_async16(sbase + SM_B + r * ROWB + c * 16,
                               wsrc + (size_t)r * F_IN + c * 8);
                }
                cp_commit();
            }

            for (int kc = 0; kc < NKC; kc++) {
                // ---- issue chunk kc+1 into the other buffer ----
                if (kc + 1 < NKC) {
                    const int buf = (kc + 1) & 1;
                    const __half* asrc = abase + (kc + 1) * KC;
                    const __half* wsrc = wbase + (kc + 1) * KC;
                    const uint32_t dA = sbase + SM_A + buf * A_BUF_B;
                    const uint32_t dB = sbase + SM_B + buf * B_BUF_B;
                    #pragma unroll
                    for (int it = 0; it < 4; it++) {
                        int idx = tid + it * THREADS;
                        int r = idx >> 3, c = idx & 7;
                        cp_async16(dA + r * ROWB + c * 16, asrc + (size_t)r * F_IN + c * 8);
                    }
                    #pragma unroll
                    for (int it = 0; it < 8; it++) {
                        int idx = tid + it * THREADS;
                        int r = idx >> 3, c = idx & 7;
                        cp_async16(dB + r * ROWB + c * 16, wsrc + (size_t)r * F_IN + c * 8);
                    }
                    cp_commit();
                    cp_wait<1>();
                } else {
                    cp_wait<0>();
                }
                __syncthreads();

                const int buf = kc & 1;
                const char* smA = smem + SM_A + buf * A_BUF_B;
                const char* smB = smem + SM_B + buf * B_BUF_B;

                #pragma unroll
                for (int ks = 0; ks < 4; ks++) {       // 4 x k16 steps = K64
                    const int kbyte = (ks * 16 + tig * 2) * 2;  // fp16 -> bytes

                    uint32_t af[4][4];
                    #pragma unroll
                    for (int mt = 0; mt < 4; mt++) {
                        const char* base = smA + (warpM + mt * 16 + gid) * ROWB + kbyte;
                        af[mt][0] = *(const uint32_t*)(base);
                        af[mt][1] = *(const uint32_t*)(base + 8 * ROWB);
                        af[mt][2] = *(const uint32_t*)(base + 16);
                        af[mt][3] = *(const uint32_t*)(base + 8 * ROWB + 16);
                    }
                    uint32_t bf[8][2];
                    #pragma unroll
                    for (int nt = 0; nt < 8; nt++) {
                        const char* base = smB + (warpN + nt * 8 + gid) * ROWB + kbyte;
                        bf[nt][0] = *(const uint32_t*)(base);
                        bf[nt][1] = *(const uint32_t*)(base + 16);
                    }
                    #pragma unroll
                    for (int mt = 0; mt < 4; mt++)
                        #pragma unroll
                        for (int nt = 0; nt < 8; nt++)
                            mma16816(acc[mt][nt][0], acc[mt][nt][1],
                                     acc[mt][nt][2], acc[mt][nt][3],
                                     af[mt][0], af[mt][1], af[mt][2], af[mt][3],
                                     bf[nt][0], bf[nt][1]);
                }
                __syncthreads();   // all warps done with buf before it is refilled
            }

            // ---- epilogue for this (p, nh) pass ----
            // thread owns rows {warpM + mt*16 + gid (+8)}, cols {warpN + nt*8 + tig*2 (+1)}
            const float* w2p = w2s + p * F_OUT;
            #pragma unroll
            for (int mt = 0; mt < 4; mt++) {
                #pragma unroll
                for (int j2 = 0; j2 < 2; j2++) {
                    const int row = warpM + mt * 16 + gid + j2 * 8;
                    float s = 0.0f;
                    #pragma unroll
                    for (int nt = 0; nt < 8; nt++) {
                        #pragma unroll
                        for (int j = 0; j < 2; j++) {
                            const int col = nh * NHALF + warpN + nt * 8 + tig * 2 + j;
                            float v = acc[mt][nt][j2 * 2 + j] + b1s[col];
                            v = __saturatef(v);
                            s = fmaf(v, w2p[col], s);
                        }
                    }
                    s += __shfl_xor_sync(0xFFFFFFFF, s, 1);
                    s += __shfl_xor_sync(0xFFFFFFFF, s, 2);
                    if (tig == 0) atomicAdd(&pacc[row], s);
                }
            }
            // no barrier needed: next pass writes buf0 only after chunk0's
            // cp.async, whose consumption is gated by wait+syncthreads.
        }
    }

    __syncthreads();
    if (tid < TILE_M) {
        float tot = pacc[tid] + b2[0];
        out[rowbase + tid] = 1.0f / (1.0f + __expf(-tot));
    }
}

// ---------------- launch ----------------
extern "C" void kernel_launch(void* const* d_in, const int* in_sizes, int n_in,
                              void* d_out, int out_size) {
    const float* stm  = (const float*)d_in[0];
    const float* nstm = (const float*)d_in[1];
    const float* W1   = (const float*)d_in[2];
    const float* b1   = (const float*)d_in[3];
    const float* W2   = (const float*)d_in[4];
    const float* b2   = (const float*)d_in[5];
    float* out = (float*)d_out;

    cvt_kernel<<<2048, 256>>>(stm, nstm, W1);

    static bool attr_set = false;
    if (!attr_set) {
        cudaFuncSetAttribute(pnet_kernel, cudaFuncAttributeMaxDynamicSharedMemorySize,
                             SMEM_TOTAL);
        attr_set = true;
    }
    pnet_kernel<<<NB / TILE_M, THREADS, SMEM_TOTAL>>>(b1, W2, b2, out);
}

// round 7
// speedup vs baseline: 1.1971x; 1.1971x over previous
#include <cuda_runtime.h>
#include <cuda_fp16.h>
#include <cstdint>

// ---------------- problem constants ----------------
#define NB      16384
#define F_IN    768
#define F_OUT   512
#define TILE_M  128          // batch rows per CTA
#define NHALF   256          // N columns per pass
#define KC      64           // K elements per SMEM chunk
#define NKC     (F_IN / KC)  // 12 chunks
#define THREADS 512

#define ROWB    144          // padded SMEM row stride in bytes (72 fp16) -> conflict-free
#define A_BUF_B (TILE_M * ROWB)   // 18432
#define B_BUF_B (NHALF  * ROWB)   // 36864

// smem layout (bytes, dynamic)
#define SM_B1    0                       // 512 f
#define SM_W2    2048                    // 1024 f
#define SM_PACC  6144                    // 128 f
#define SM_A     6912                    // 2 x 18432
#define SM_B     (6912 + 2*A_BUF_B)      // 2 x 36864
#define SMEM_TOTAL (SM_B + 2*B_BUF_B)    // 117504 bytes

// ---------------- fp16 weights scratch (device global: allowed) ----------------
__device__ __align__(16) __half g_w16[F_OUT * F_IN];

// ---------------- helpers ----------------
__device__ __forceinline__ uint32_t smem_u32(const void* p) {
    uint32_t a;
    asm("{ .reg .u64 t; cvta.to.shared.u64 t, %1; cvt.u32.u64 %0, t; }" : "=r"(a) : "l"(p));
    return a;
}

__device__ __forceinline__ void cp_async16(uint32_t dst, const void* src) {
    asm volatile("cp.async.cg.shared.global [%0], [%1], 16;\n" :: "r"(dst), "l"(src) : "memory");
}
__device__ __forceinline__ void cp_commit() {
    asm volatile("cp.async.commit_group;\n" ::: "memory");
}
template <int N>
__device__ __forceinline__ void cp_wait() {
    asm volatile("cp.async.wait_group %0;\n" :: "n"(N) : "memory");
}

__device__ __forceinline__ void ldsm_x4(uint32_t& r0, uint32_t& r1, uint32_t& r2, uint32_t& r3,
                                        uint32_t addr) {
    asm volatile("ldmatrix.sync.aligned.m8n8.x4.shared.b16 {%0,%1,%2,%3}, [%4];"
                 : "=r"(r0), "=r"(r1), "=r"(r2), "=r"(r3) : "r"(addr));
}

__device__ __forceinline__ void mma16816(float& c0, float& c1, float& c2, float& c3,
                                         uint32_t a0, uint32_t a1, uint32_t a2, uint32_t a3,
                                         uint32_t b0, uint32_t b1) {
    asm volatile(
        "mma.sync.aligned.m16n8k16.row.col.f32.f16.f16.f32 "
        "{%0,%1,%2,%3}, {%4,%5,%6,%7}, {%8,%9}, {%0,%1,%2,%3};"
        : "+f"(c0), "+f"(c1), "+f"(c2), "+f"(c3)
        : "r"(a0), "r"(a1), "r"(a2), "r"(a3), "r"(b0), "r"(b1));
}

// ---------------- prologue: W1 fp32 -> fp16 (0.75 MB, ~2us) ----------------
__global__ void cvt_w_kernel(const float* __restrict__ W1) {
    int i = blockIdx.x * blockDim.x + threadIdx.x;   // float4 index, total 98304
    float4 v = ((const float4*)W1)[i];
    __half2 h0 = __floats2half2_rn(v.x, v.y);
    __half2 h1 = __floats2half2_rn(v.z, v.w);
    uint2 pk;
    pk.x = *(uint32_t*)&h0;
    pk.y = *(uint32_t*)&h1;
    ((uint2*)g_w16)[i] = pk;
}

// ---------------- main fused kernel ----------------
__global__ void __launch_bounds__(THREADS, 1)
pnet_kernel(const float* __restrict__ stm, const float* __restrict__ nstm,
            const float* __restrict__ b1,  const float* __restrict__ W2,
            const float* __restrict__ b2,  float* __restrict__ out)
{
    extern __shared__ char smem[];
    const uint32_t sbase = smem_u32(smem);
    const int tid  = threadIdx.x;
    const int wid  = tid >> 5;
    const int lane = tid & 31;
    const int gid  = lane >> 2;   // row within 8 for MMA fragments
    const int tig  = lane & 3;    // col-pair / k-pair within fragment

    const int warpM = (wid & 3) * 32;   // 4 warps along M (128 rows)
    const int warpN = (wid >> 2) * 64;  // 4 warps along N (256 cols)

    float* b1s  = (float*)(smem + SM_B1);
    float* w2s  = (float*)(smem + SM_W2);
    float* pacc = (float*)(smem + SM_PACC);

    for (int i = tid; i < F_OUT; i += THREADS)     b1s[i] = b1[i];
    for (int i = tid; i < 2 * F_OUT; i += THREADS) w2s[i] = W2[i];
    if (tid < TILE_M) pacc[tid] = 0.0f;
    __syncthreads();

    const int rowbase = blockIdx.x * TILE_M;

    // per-thread load geometry
    const int ar = tid >> 4;      // A row base (it adds 32); 16 float4 per 64-col row
    const int ac = tid & 15;      // A float4 col
    const int br = tid >> 3;      // B row base (it adds 64); 8x16B per row
    const int bc = tid & 7;       // B 16B col

    // ldmatrix lane address components
    const int lrow = lane & 15;
    const int lhi  = (lane >> 4) * 16;

    for (int p = 0; p < 2; p++) {
        const float* abase = (p ? nstm : stm) + (size_t)rowbase * F_IN;

        for (int nh = 0; nh < 2; nh++) {
            const __half* wbase = g_w16 + (size_t)nh * NHALF * F_IN;

            float acc[2][8][4];
            #pragma unroll
            for (int mt = 0; mt < 2; mt++)
                #pragma unroll
                for (int nt = 0; nt < 8; nt++)
                    #pragma unroll
                    for (int e = 0; e < 4; e++) acc[mt][nt][e] = 0.0f;

            // ---- prefetch chunk 0: A fp32 -> regs, B fp16 -> smem via cp.async ----
            float4 regA[4];
            #pragma unroll
            for (int it = 0; it < 4; it++)
                regA[it] = *(const float4*)(abase + (size_t)(ar + 32 * it) * F_IN + ac * 4);
            #pragma unroll
            for (int it = 0; it < 4; it++)
                cp_async16(sbase + SM_B + (br + 64 * it) * ROWB + bc * 16,
                           wbase + (size_t)(br + 64 * it) * F_IN + bc * 8);
            cp_commit();

            for (int kc = 0; kc < NKC; kc++) {
                const int buf = kc & 1;

                // convert + store A(kc) into this chunk's buffer
                #pragma unroll
                for (int it = 0; it < 4; it++) {
                    __half2 h0 = __floats2half2_rn(regA[it].x, regA[it].y);
                    __half2 h1 = __floats2half2_rn(regA[it].z, regA[it].w);
                    uint2 pk;
                    pk.x = *(uint32_t*)&h0;
                    pk.y = *(uint32_t*)&h1;
                    *(uint2*)(smem + SM_A + buf * A_BUF_B + (ar + 32 * it) * ROWB + ac * 8) = pk;
                }

                if (kc + 1 < NKC) {
                    // prefetch next chunk: A fp32 LDG (hidden behind this chunk's MMAs)
                    const float* asrc = abase + (kc + 1) * KC;
                    #pragma unroll
                    for (int it = 0; it < 4; it++)
                        regA[it] = *(const float4*)(asrc + (size_t)(ar + 32 * it) * F_IN + ac * 4);
                    // B fp16 cp.async into other buffer
                    const __half* wsrc = wbase + (kc + 1) * KC;
                    const uint32_t dB = sbase + SM_B + ((kc + 1) & 1) * B_BUF_B;
                    #pragma unroll
                    for (int it = 0; it < 4; it++)
                        cp_async16(dB + (br + 64 * it) * ROWB + bc * 16,
                                   wsrc + (size_t)(br + 64 * it) * F_IN + bc * 8);
                    cp_commit();
                    cp_wait<1>();
                } else {
                    cp_wait<0>();
                }
                __syncthreads();   // A STS visible + B(kc) complete

                const uint32_t smA = sbase + SM_A + buf * A_BUF_B;
                const uint32_t smB = sbase + SM_B + buf * B_BUF_B;

                #pragma unroll
                for (int ks = 0; ks < 4; ks++) {       // 4 x k16 steps = K64
                    const int kb = ks * 32 + lhi;

                    uint32_t af[2][4];
                    #pragma unroll
                    for (int mt = 0; mt < 2; mt++)
                        ldsm_x4(af[mt][0], af[mt][1], af[mt][2], af[mt][3],
                                smA + (warpM + mt * 16 + lrow) * ROWB + kb);

                    #pragma unroll
                    for (int nb = 0; nb < 4; nb++) {
                        uint32_t t0, t1, t2, t3;
                        ldsm_x4(t0, t1, t2, t3,
                                smB + (warpN + nb * 16 + lrow) * ROWB + kb);
                        #pragma unroll
                        for (int mt = 0; mt < 2; mt++) {
                            mma16816(acc[mt][2 * nb][0], acc[mt][2 * nb][1],
                                     acc[mt][2 * nb][2], acc[mt][2 * nb][3],
                                     af[mt][0], af[mt][1], af[mt][2], af[mt][3], t0, t2);
                            mma16816(acc[mt][2 * nb + 1][0], acc[mt][2 * nb + 1][1],
                                     acc[mt][2 * nb + 1][2], acc[mt][2 * nb + 1][3],
                                     af[mt][0], af[mt][1], af[mt][2], af[mt][3], t1, t3);
                        }
                    }
                }
                __syncthreads();   // all warps done reading before buffers are refilled
            }

            // ---- epilogue for this (p, nh) pass ----
            const float* w2p = w2s + p * F_OUT;
            #pragma unroll
            for (int mt = 0; mt < 2; mt++) {
                #pragma unroll
                for (int j2 = 0; j2 < 2; j2++) {
                    const int row = warpM + mt * 16 + gid + j2 * 8;
                    float s = 0.0f;
                    #pragma unroll
                    for (int nt = 0; nt < 8; nt++) {
                        #pragma unroll
                        for (int j = 0; j < 2; j++) {
                            const int col = nh * NHALF + warpN + nt * 8 + tig * 2 + j;
                            float v = acc[mt][nt][j2 * 2 + j] + b1s[col];
                            v = __saturatef(v);
                            s = fmaf(v, w2p[col], s);
                        }
                    }
                    s += __shfl_xor_sync(0xFFFFFFFF, s, 1);
                    s += __shfl_xor_sync(0xFFFFFFFF, s, 2);
                    if (tig == 0) atomicAdd(&pacc[row], s);
                }
            }
        }
    }

    __syncthreads();
    if (tid < TILE_M) {
        float tot = pacc[tid] + b2[0];
        out[rowbase + tid] = 1.0f / (1.0f + __expf(-tot));
    }
}

// ---------------- launch ----------------
extern "C" void kernel_launch(void* const* d_in, const int* in_sizes, int n_in,
                              void* d_out, int out_size) {
    const float* stm  = (const float*)d_in[0];
    const float* nstm = (const float*)d_in[1];
    const float* W1   = (const float*)d_in[2];
    const float* b1   = (const float*)d_in[3];
    const float* W2   = (const float*)d_in[4];
    const float* b2   = (const float*)d_in[5];
    float* out = (float*)d_out;

    cvt_w_kernel<<<(F_OUT * F_IN / 4) / 256, 256>>>(W1);

    cudaFuncSetAttribute(pnet_kernel, cudaFuncAttributeMaxDynamicSharedMemorySize, SMEM_TOTAL);
    pnet_kernel<<<NB / TILE_M, THREADS, SMEM_TOTAL>>>(stm, nstm, b1, W2, b2, out);
}